// round 5
// baseline (speedup 1.0000x reference)
#include <cuda_runtime.h>
#include <math.h>
#include <stdint.h>

// Shapes (fixed): U=256, D=5120, N=16, R=160
#define U_DIM 256
#define D_DIM 5120
#define N_DIM 16
#define R_DIM 160
#define NCOL  176   // 160 (t) + 16 (B)
#define NPAD  192   // padded col space: 3 col-pairs x 32 lanes

typedef unsigned long long ull;

// ---------------- scratch ----------------
#define S1_SPLITS 80
#define S1_KC     64      // K per split (2 stages of 32)
#define S1_KK     32      // K per smem stage
#define S1_UT     64      // users per block
#define XPITCH    66      // xsh pitch in ull (even -> 16B-aligned v2 reads)

__device__ float g_partial[S1_SPLITS * U_DIM * NCOL];   // 14.4 MB
__device__ float g_tbuf[U_DIM * NCOL];                  // t | B

// ---------------- f32x2 helpers ----------------
__device__ __forceinline__ ull pack2(float v) {
    ull r; asm("mov.b64 %0, {%1, %1};" : "=l"(r) : "f"(v)); return r;
}
__device__ __forceinline__ void fma2(ull& acc, ull a, ull b) {
    asm("fma.rn.f32x2 %0, %1, %2, %0;" : "+l"(acc) : "l"(a), "l"(b));
}
__device__ __forceinline__ void lds_v2b64(ull& a, ull& b, uint32_t addr) {
    asm volatile("ld.shared.v2.b64 {%0, %1}, [%2];" : "=l"(a), "=l"(b) : "r"(addr));
}
__device__ __forceinline__ ull lds_b64(uint32_t addr) {
    ull a; asm volatile("ld.shared.b64 %0, [%1];" : "=l"(a) : "r"(addr)); return a;
}

// ================= Stage 1: split-K GEMM  t_ext[U,176] = x @ [W1 | Bp] ==========
// grid (4 u-tiles, 80 k-splits), block 256 (8 warps).
// Warp w owns users w*8..w*8+7. Lane cx owns col-pairs (64c + 2cx, +1), c=0..2.
__global__ void __launch_bounds__(256) stage1_kernel(
    const float* __restrict__ x,
    const float* __restrict__ W1,   // [5120,160]
    const float* __restrict__ Bp)   // [5120,16]
{
    __shared__ __align__(16) ull   xsh[S1_KK * XPITCH];    // {x,x} per user, 16.5KB
    __shared__ __align__(16) float wsh[S1_KK * NPAD];      // [k][col], 24KB

    const int tid = threadIdx.x;
    const int cx  = tid & 31;
    const int wid = tid >> 5;
    const int u0  = blockIdx.x * S1_UT;
    const int k0  = blockIdx.y * S1_KC;

    ull acc[8][3];
#pragma unroll
    for (int uu = 0; uu < 8; ++uu)
#pragma unroll
        for (int c = 0; c < 3; ++c) acc[uu][c] = 0ULL;

    const uint32_t xb = (uint32_t)__cvta_generic_to_shared(xsh);
    const uint32_t wb = (uint32_t)__cvta_generic_to_shared(wsh);

#pragma unroll
    for (int st = 0; st < S1_KC / S1_KK; ++st) {
        const int kb = k0 + st * S1_KK;
        // stage x duplicated: xsh[k*66 + u] = {x,x}
        for (int e = tid; e < S1_UT * S1_KK; e += 256) {
            int u = e >> 5, k = e & 31;
            xsh[k * XPITCH + u] = pack2(x[(size_t)(u0 + u) * D_DIM + kb + k]);
        }
        // stage W1 rows (cols 0..159)
        for (int e = tid; e < S1_KK * R_DIM; e += 256) {
            int k = e / R_DIM, r = e - k * R_DIM;
            wsh[k * NPAD + r] = W1[(size_t)(kb + k) * R_DIM + r];
        }
        // stage Bp rows -> cols 160..175 (176..191 left stale: discarded at writeout)
        for (int e = tid; e < S1_KK * N_DIM; e += 256) {
            int k = e >> 4, n = e & 15;
            wsh[k * NPAD + R_DIM + n] = Bp[(size_t)(kb + k) * N_DIM + n];
        }
        __syncthreads();

#pragma unroll 4
        for (int kk = 0; kk < S1_KK; ++kk) {
            ull xp[8];
            const uint32_t xa = xb + (uint32_t)(kk * XPITCH + wid * 8) * 8u;
            lds_v2b64(xp[0], xp[1], xa);
            lds_v2b64(xp[2], xp[3], xa + 16u);
            lds_v2b64(xp[4], xp[5], xa + 32u);
            lds_v2b64(xp[6], xp[7], xa + 48u);
            const uint32_t wa = wb + (uint32_t)(kk * NPAD + 2 * cx) * 4u;
            ull wp[3];
            wp[0] = lds_b64(wa);
            wp[1] = lds_b64(wa + 256u);
            wp[2] = lds_b64(wa + 512u);
#pragma unroll
            for (int c = 0; c < 3; ++c)
#pragma unroll
                for (int uu = 0; uu < 8; ++uu) fma2(acc[uu][c], xp[uu], wp[c]);
        }
        __syncthreads();
    }

    // writeout: packed 8B stores of col-pairs (64c+2cx, +1); pair valid iff c<2 || cx<24
    float* pout = g_partial + (size_t)blockIdx.y * (U_DIM * NCOL);
#pragma unroll
    for (int uu = 0; uu < 8; ++uu) {
        const int u = u0 + wid * 8 + uu;
#pragma unroll
        for (int c = 0; c < 3; ++c) {
            if (c < 2 || cx < 24) {
                const int col = 64 * c + 2 * cx;
                *(ull*)(pout + (size_t)u * NCOL + col) = acc[uu][c];
            }
        }
    }
}

// ================= Stage 2: reduce 80 split partials (float4) ===================
#define RED_F4 (U_DIM * NCOL / 4)   // 11264
__global__ void __launch_bounds__(256) reduce_kernel() {
    const int idx = blockIdx.x * 256 + threadIdx.x;   // 44 * 256 == 11264 exactly
    const float4* p4 = (const float4*)g_partial;
    float4 s = make_float4(0.f, 0.f, 0.f, 0.f);
#pragma unroll 8
    for (int sp = 0; sp < S1_SPLITS; ++sp) {
        float4 v = __ldcg(p4 + (size_t)sp * RED_F4 + idx);
        s.x += v.x; s.y += v.y; s.z += v.z; s.w += v.w;
    }
    ((float4*)g_tbuf)[idx] = s;
}

// ================= Stage 3: fused dt-GEMM + softplus + streaming ================
#define FU_UT 16
#define FU_DT 128
#define CH 8   // W2 prefetch chunk (r rows)

__global__ void __launch_bounds__(256, 4) fused_kernel(
    const float* __restrict__ W2,    // [160,5120]
    const float* __restrict__ bias,  // [5120]
    const float* __restrict__ x,     // [256,5120]
    const float4* __restrict__ abar4,
    const float4* __restrict__ hst4,
    float4* __restrict__ out4)
{
    __shared__ __align__(16) float tsh[R_DIM * FU_UT];     // [r][u] 10.2 KB
    __shared__ __align__(16) float c1sh[FU_UT * FU_DT];    // 8 KB
    __shared__ __align__(16) float Bsh[FU_UT * N_DIM];     // 1 KB

    const int u0  = blockIdx.x * FU_UT;
    const int d0  = blockIdx.y * FU_DT;
    const int tid = threadIdx.x;

    const int dl = tid & 127;
    const int ug = (tid >> 7) * 8;     // 0 or 8
    const int d  = d0 + dl;
    const float* wp = W2 + d;

    // preload W2 chunks 0 and 1 (overlaps with staging + sync)
    float bufA[CH], bufB[CH];
#pragma unroll
    for (int i = 0; i < CH; ++i) bufA[i] = __ldg(wp + (size_t)i * D_DIM);
#pragma unroll
    for (int i = 0; i < CH; ++i) bufB[i] = __ldg(wp + (size_t)(CH + i) * D_DIM);

    // stage t transposed: tsh[r*16 + u]
    for (int e = tid; e < FU_UT * R_DIM; e += 256) {
        int u = e / R_DIM, r = e - u * R_DIM;
        tsh[r * FU_UT + u] = g_tbuf[(size_t)(u0 + u) * NCOL + r];
    }
    // stage B: tid covers 16u x 16n exactly
    {
        int u = tid >> 4, n = tid & 15;
        Bsh[tid] = g_tbuf[(size_t)(u0 + u) * NCOL + R_DIM + n];
    }
    __syncthreads();

    // ---- GEMM phase: 20 chunks of 8 r, distance-2 register double buffer ----
    ull acc[4];
#pragma unroll
    for (int i = 0; i < 4; ++i) acc[i] = 0ULL;
    const uint32_t tb = (uint32_t)__cvta_generic_to_shared(tsh) + (uint32_t)ug * 4u;

#pragma unroll 1
    for (int c = 0; c < 20; c += 2) {
#pragma unroll
        for (int i = 0; i < CH; ++i) {
            const int r = c * CH + i;
            const ull w2 = pack2(bufA[i]);
            const uint32_t a = tb + (uint32_t)(r * FU_UT) * 4u;
            ull p0, p1, p2, p3;
            lds_v2b64(p0, p1, a);
            lds_v2b64(p2, p3, a + 16u);
            fma2(acc[0], p0, w2); fma2(acc[1], p1, w2);
            fma2(acc[2], p2, w2); fma2(acc[3], p3, w2);
        }
        if (c + 2 < 20) {
#pragma unroll
            for (int i = 0; i < CH; ++i)
                bufA[i] = __ldg(wp + (size_t)((c + 2) * CH + i) * D_DIM);
        }
#pragma unroll
        for (int i = 0; i < CH; ++i) {
            const int r = (c + 1) * CH + i;
            const ull w2 = pack2(bufB[i]);
            const uint32_t a = tb + (uint32_t)(r * FU_UT) * 4u;
            ull p0, p1, p2, p3;
            lds_v2b64(p0, p1, a);
            lds_v2b64(p2, p3, a + 16u);
            fma2(acc[0], p0, w2); fma2(acc[1], p1, w2);
            fma2(acc[2], p2, w2); fma2(acc[3], p3, w2);
        }
        if (c + 3 < 20) {
#pragma unroll
            for (int i = 0; i < CH; ++i)
                bufB[i] = __ldg(wp + (size_t)((c + 3) * CH + i) * D_DIM);
        }
    }

    const float bz = bias[d];
#pragma unroll
    for (int i = 0; i < 4; ++i) {
        float z0, z1;
        asm("mov.b64 {%0, %1}, %2;" : "=f"(z0), "=f"(z1) : "l"(acc[i]));
        const int u = ug + 2 * i;
        z0 += bz; z1 += bz;
        const float dt0 = fmaxf(z0, 0.f) + log1pf(expf(-fabsf(z0)));
        const float dt1 = fmaxf(z1, 0.f) + log1pf(expf(-fabsf(z1)));
        c1sh[u * FU_DT + dl]       = dt0 * __ldg(x + (size_t)(u0 + u) * D_DIM + d);
        c1sh[(u + 1) * FU_DT + dl] = dt1 * __ldg(x + (size_t)(u0 + u + 1) * D_DIM + d);
    }
    __syncthreads();

    // ---- streaming phase ----
    const int n4 = tid & 3;
    const int i0 = tid;
    const int i1 = tid + 256;

#pragma unroll 2
    for (int u = 0; u < FU_UT; ++u) {
        const size_t base = ((size_t)(u0 + u) * D_DIM + d0) * 4;  // float4 units
        const float4 b = *(const float4*)(Bsh + u * N_DIM + n4 * 4);
        const float c0 = c1sh[u * FU_DT + (i0 >> 2)];
        const float c1 = c1sh[u * FU_DT + (i1 >> 2)];

        const float4 a0 = __ldcs(abar4 + base + i0);
        const float4 h0 = __ldcs(hst4  + base + i0);
        const float4 a1 = __ldcs(abar4 + base + i1);
        const float4 h1 = __ldcs(hst4  + base + i1);

        float4 o0, o1;
        o0.x = fmaf(a0.x, h0.x, c0 * b.x);
        o0.y = fmaf(a0.y, h0.y, c0 * b.y);
        o0.z = fmaf(a0.z, h0.z, c0 * b.z);
        o0.w = fmaf(a0.w, h0.w, c0 * b.w);
        o1.x = fmaf(a1.x, h1.x, c1 * b.x);
        o1.y = fmaf(a1.y, h1.y, c1 * b.y);
        o1.z = fmaf(a1.z, h1.z, c1 * b.z);
        o1.w = fmaf(a1.w, h1.w, c1 * b.w);
        __stcs(out4 + base + i0, o0);
        __stcs(out4 + base + i1, o1);
    }
}

extern "C" void kernel_launch(void* const* d_in, const int* in_sizes, int n_in,
                              void* d_out, int out_size) {
    const float* x    = (const float*)d_in[0];   // [256,5120]
    const float* W1   = (const float*)d_in[1];   // [5120,160]
    const float* W2   = (const float*)d_in[2];   // [160,5120]
    const float* bias = (const float*)d_in[3];   // [5120]
    const float* Bp   = (const float*)d_in[4];   // [5120,16]
    const float* abar = (const float*)d_in[5];   // [256,5120,16]
    const float* hst  = (const float*)d_in[6];   // [256,5120,16]
    float* out = (float*)d_out;

    stage1_kernel<<<dim3(U_DIM / S1_UT, S1_SPLITS), 256>>>(x, W1, Bp);
    reduce_kernel<<<RED_F4 / 256, 256>>>();
    fused_kernel<<<dim3(U_DIM / FU_UT, D_DIM / FU_DT), 256>>>(
        W2, bias, x, (const float4*)abar, (const float4*)hst, (float4*)out);
}

// round 6
// speedup vs baseline: 1.0591x; 1.0591x over previous
#include <cuda_runtime.h>
#include <math.h>
#include <stdint.h>

// Shapes (fixed): U=256, D=5120, N=16, R=160
#define U_DIM 256
#define D_DIM 5120
#define N_DIM 16
#define R_DIM 160
#define NCOL  176   // 160 (t) + 16 (B)
#define NPAD  192   // padded col space: 3 col-pairs x 32 lanes

typedef unsigned long long ull;

// ---------------- scratch ----------------
#define S1_SPLITS 160
#define S1_KC     32      // K per split (single smem stage)
#define S1_UT     64      // users per block
#define XPITCH    66      // xsh pitch in ull (even -> 16B-aligned v2 reads)

__device__ float g_partial[S1_SPLITS * U_DIM * NCOL];   // 28.8 MB
__device__ float g_tbuf[U_DIM * NCOL];                  // t | B

// ---------------- helpers ----------------
__device__ __forceinline__ ull pack2(float v) {
    ull r; asm("mov.b64 %0, {%1, %1};" : "=l"(r) : "f"(v)); return r;
}
__device__ __forceinline__ ull combine2(float lo, float hi) {
    ull r; asm("mov.b64 %0, {%1, %2};" : "=l"(r) : "f"(lo), "f"(hi)); return r;
}
__device__ __forceinline__ void fma2(ull& acc, ull a, ull b) {
    asm("fma.rn.f32x2 %0, %1, %2, %0;" : "+l"(acc) : "l"(a), "l"(b));
}
__device__ __forceinline__ void lds_v2b64(ull& a, ull& b, uint32_t addr) {
    asm volatile("ld.shared.v2.b64 {%0, %1}, [%2];" : "=l"(a), "=l"(b) : "r"(addr));
}
__device__ __forceinline__ ull lds_b64(uint32_t addr) {
    ull a; asm volatile("ld.shared.b64 %0, [%1];" : "=l"(a) : "r"(addr)); return a;
}
__device__ __forceinline__ void cp16(uint32_t dst, const void* src) {
    asm volatile("cp.async.ca.shared.global [%0], [%1], 16;" :: "r"(dst), "l"(src));
}
__device__ __forceinline__ void cp_commit() {
    asm volatile("cp.async.commit_group;");
}
__device__ __forceinline__ void cp_wait0() {
    asm volatile("cp.async.wait_group 0;");
}

// ================= Stage 1: split-K GEMM  t_ext[U,176] = x @ [W1 | Bp] ==========
// grid (4 u-tiles, 160 k-splits), block 256 (8 warps), single 32-k smem stage.
// Warp w owns users w*8..w*8+7. Lane cx owns col-pairs (64c + 2cx, +1), c=0..2.
__global__ void __launch_bounds__(256) stage1_kernel(
    const float* __restrict__ x,
    const float* __restrict__ W1,   // [5120,160]
    const float* __restrict__ Bp)   // [5120,16]
{
    __shared__ __align__(16) ull   xsh[S1_KC * XPITCH];    // {x,x} dup, 16.9KB
    __shared__ __align__(16) float wsh[S1_KC * NPAD];      // [k][col], 24.6KB

    const int tid = threadIdx.x;
    const int cx  = tid & 31;
    const int wid = tid >> 5;
    const int u0  = blockIdx.x * S1_UT;
    const int k0  = blockIdx.y * S1_KC;

    const uint32_t xb = (uint32_t)__cvta_generic_to_shared(xsh);
    const uint32_t wb = (uint32_t)__cvta_generic_to_shared(wsh);

    // async-stage W1: 32 rows x 160 floats = 40 x 16B chunks per row
    for (int ch = tid; ch < S1_KC * 40; ch += 256) {
        int k = ch / 40, c = ch - k * 40;
        cp16(wb + (uint32_t)(k * NPAD + c * 4) * 4u,
             W1 + (size_t)(k0 + k) * R_DIM + c * 4);
    }
    // async-stage Bp: 32 rows x 16 floats = 4 chunks per row
    if (tid < S1_KC * 4) {
        int k = tid >> 2, c = tid & 3;
        cp16(wb + (uint32_t)(k * NPAD + R_DIM + c * 4) * 4u,
             Bp + (size_t)(k0 + k) * N_DIM + c * 4);
    }
    cp_commit();

    // stage x duplicated: xsh[k*66 + u] = {x,x}  (overlaps with cp.async)
    for (int e = tid; e < S1_UT * S1_KC; e += 256) {
        int u = e >> 5, k = e & 31;
        xsh[k * XPITCH + u] = pack2(x[(size_t)(u0 + u) * D_DIM + k0 + k]);
    }

    ull acc[8][3];
#pragma unroll
    for (int uu = 0; uu < 8; ++uu)
#pragma unroll
        for (int c = 0; c < 3; ++c) acc[uu][c] = 0ULL;

    cp_wait0();
    __syncthreads();

#pragma unroll 4
    for (int kk = 0; kk < S1_KC; ++kk) {
        ull xp[8];
        const uint32_t xa = xb + (uint32_t)(kk * XPITCH + wid * 8) * 8u;
        lds_v2b64(xp[0], xp[1], xa);
        lds_v2b64(xp[2], xp[3], xa + 16u);
        lds_v2b64(xp[4], xp[5], xa + 32u);
        lds_v2b64(xp[6], xp[7], xa + 48u);
        const uint32_t wa = wb + (uint32_t)(kk * NPAD + 2 * cx) * 4u;
        ull wp[3];
        wp[0] = lds_b64(wa);
        wp[1] = lds_b64(wa + 256u);
        wp[2] = lds_b64(wa + 512u);
#pragma unroll
        for (int c = 0; c < 3; ++c)
#pragma unroll
            for (int uu = 0; uu < 8; ++uu) fma2(acc[uu][c], xp[uu], wp[c]);
    }

    // writeout: packed 8B stores of col-pairs (64c+2cx, +1); pair valid iff c<2 || cx<24
    float* pout = g_partial + (size_t)blockIdx.y * (U_DIM * NCOL);
#pragma unroll
    for (int uu = 0; uu < 8; ++uu) {
        const int u = u0 + wid * 8 + uu;
#pragma unroll
        for (int c = 0; c < 3; ++c) {
            if (c < 2 || cx < 24) {
                const int col = 64 * c + 2 * cx;
                *(ull*)(pout + (size_t)u * NCOL + col) = acc[uu][c];
            }
        }
    }
}

// ================= Stage 2: reduce 160 split partials (float4) ==================
#define RED_F4 (U_DIM * NCOL / 4)   // 11264
__global__ void __launch_bounds__(256) reduce_kernel() {
    const int idx = blockIdx.x * 256 + threadIdx.x;   // 44 * 256 == 11264 exactly
    const float4* p4 = (const float4*)g_partial;
    float4 s = make_float4(0.f, 0.f, 0.f, 0.f);
#pragma unroll 10
    for (int sp = 0; sp < S1_SPLITS; ++sp) {
        float4 v = __ldcg(p4 + (size_t)sp * RED_F4 + idx);
        s.x += v.x; s.y += v.y; s.z += v.z; s.w += v.w;
    }
    ((float4*)g_tbuf)[idx] = s;
}

// ================= Stage 3: fused dt-GEMM + softplus + streaming ================
// Block: 16 users x 128 d. W2 double-buffered via cp.async in 16-row chunks.
#define FU_UT 16
#define FU_DT 128
#define RCH 16                 // r rows per chunk
#define NCH (R_DIM / RCH)      // 10 chunks
#define W2CHUNK (RCH * FU_DT)  // floats per chunk (2048)

__global__ void __launch_bounds__(256, 5) fused_kernel(
    const float* __restrict__ W2,    // [160,5120]
    const float* __restrict__ bias,  // [5120]
    const float* __restrict__ x,     // [256,5120]
    const float4* __restrict__ abar4,
    const float4* __restrict__ hst4,
    float4* __restrict__ out4)
{
    __shared__ __align__(16) ull   tpair[R_DIM * 8];          // {t_u,t_u+1} 10.2 KB
    __shared__ __align__(16) float w2sh[2 * W2CHUNK];         // 16 KB ping-pong
    __shared__ __align__(16) float c1sh[FU_UT * FU_DT];       // 8 KB
    __shared__ __align__(16) float Bsh[FU_UT * N_DIM];        // 1 KB

    const int u0  = blockIdx.x * FU_UT;
    const int d0  = blockIdx.y * FU_DT;
    const int tid = threadIdx.x;

    const uint32_t w2b = (uint32_t)__cvta_generic_to_shared(w2sh);
    const uint32_t tpb = (uint32_t)__cvta_generic_to_shared(tpair);

    // prefetch W2 chunk 0 (rows 0..15): 512 x 16B chunks
    {
        int ch = tid;            // threads 0..255 then +256
#pragma unroll
        for (int q = 0; q < 2; ++q, ch += 256) {
            int row = ch >> 5, c = ch & 31;
            cp16(w2b + (uint32_t)(row * FU_DT + c * 4) * 4u,
                 W2 + (size_t)row * D_DIM + d0 + c * 4);
        }
    }
    cp_commit();

    // stage t as user-pairs: tpair[r*8 + p] = {t[u0+2p][r], t[u0+2p+1][r]}
    for (int e = tid; e < R_DIM * 8; e += 256) {
        int r = e >> 3, p = e & 7;
        float lo = g_tbuf[(size_t)(u0 + 2 * p)     * NCOL + r];
        float hi = g_tbuf[(size_t)(u0 + 2 * p + 1) * NCOL + r];
        tpair[r * 8 + p] = combine2(lo, hi);
    }
    // stage B: tid covers 16u x 16n exactly
    {
        int u = tid >> 4, n = tid & 15;
        Bsh[tid] = g_tbuf[(size_t)(u0 + u) * NCOL + R_DIM + n];
    }

    // ---- GEMM phase: 10 chunks of 16 r, cp.async one-stage lookahead ----
    const int dl  = tid & 127;
    const int pg  = (tid >> 7) * 4;    // pair-group base: 0 or 4
    const int d   = d0 + dl;

    ull acc[4];
#pragma unroll
    for (int i = 0; i < 4; ++i) acc[i] = 0ULL;

#pragma unroll 1
    for (int s = 0; s < NCH; ++s) {
        cp_wait0();            // chunk s landed (overlapped with compute s-1)
        __syncthreads();       // all threads done with buffer (s+1)&1's old data
        if (s + 1 < NCH) {
            int ch = tid;
#pragma unroll
            for (int q = 0; q < 2; ++q, ch += 256) {
                int row = ch >> 5, c = ch & 31;
                cp16(w2b + (uint32_t)(((s + 1) & 1) * W2CHUNK + row * FU_DT + c * 4) * 4u,
                     W2 + (size_t)((s + 1) * RCH + row) * D_DIM + d0 + c * 4);
            }
            cp_commit();
        }
        const uint32_t wbase = w2b + (uint32_t)((s & 1) * W2CHUNK + dl) * 4u;
        const uint32_t tbase = tpb + (uint32_t)(s * RCH * 8 + pg) * 8u;
#pragma unroll
        for (int rr = 0; rr < RCH; ++rr) {
            float wv;
            asm volatile("ld.shared.b32 %0, [%1];"
                         : "=f"(wv) : "r"(wbase + (uint32_t)(rr * FU_DT) * 4u));
            const ull w2 = pack2(wv);
            ull p0, p1, p2, p3;
            const uint32_t ta = tbase + (uint32_t)(rr * 8) * 8u;
            lds_v2b64(p0, p1, ta);
            lds_v2b64(p2, p3, ta + 16u);
            fma2(acc[0], p0, w2); fma2(acc[1], p1, w2);
            fma2(acc[2], p2, w2); fma2(acc[3], p3, w2);
        }
    }

    const float bz = bias[d];
    const int ug = (tid >> 7) * 8;
#pragma unroll
    for (int i = 0; i < 4; ++i) {
        float z0, z1;
        asm("mov.b64 {%0, %1}, %2;" : "=f"(z0), "=f"(z1) : "l"(acc[i]));
        const int u = ug + 2 * i;
        z0 += bz; z1 += bz;
        const float dt0 = fmaxf(z0, 0.f) + log1pf(expf(-fabsf(z0)));
        const float dt1 = fmaxf(z1, 0.f) + log1pf(expf(-fabsf(z1)));
        c1sh[u * FU_DT + dl]       = dt0 * __ldg(x + (size_t)(u0 + u) * D_DIM + d);
        c1sh[(u + 1) * FU_DT + dl] = dt1 * __ldg(x + (size_t)(u0 + u + 1) * D_DIM + d);
    }
    __syncthreads();

    // ---- streaming phase ----
    const int n4 = tid & 3;
    const int i0 = tid;
    const int i1 = tid + 256;

#pragma unroll 2
    for (int u = 0; u < FU_UT; ++u) {
        const size_t base = ((size_t)(u0 + u) * D_DIM + d0) * 4;  // float4 units
        const float4 b = *(const float4*)(Bsh + u * N_DIM + n4 * 4);
        const float c0 = c1sh[u * FU_DT + (i0 >> 2)];
        const float c1 = c1sh[u * FU_DT + (i1 >> 2)];

        const float4 a0 = __ldcs(abar4 + base + i0);
        const float4 h0 = __ldcs(hst4  + base + i0);
        const float4 a1 = __ldcs(abar4 + base + i1);
        const float4 h1 = __ldcs(hst4  + base + i1);

        float4 o0, o1;
        o0.x = fmaf(a0.x, h0.x, c0 * b.x);
        o0.y = fmaf(a0.y, h0.y, c0 * b.y);
        o0.z = fmaf(a0.z, h0.z, c0 * b.z);
        o0.w = fmaf(a0.w, h0.w, c0 * b.w);
        o1.x = fmaf(a1.x, h1.x, c1 * b.x);
        o1.y = fmaf(a1.y, h1.y, c1 * b.y);
        o1.z = fmaf(a1.z, h1.z, c1 * b.z);
        o1.w = fmaf(a1.w, h1.w, c1 * b.w);
        __stcs(out4 + base + i0, o0);
        __stcs(out4 + base + i1, o1);
    }
}

extern "C" void kernel_launch(void* const* d_in, const int* in_sizes, int n_in,
                              void* d_out, int out_size) {
    const float* x    = (const float*)d_in[0];   // [256,5120]
    const float* W1   = (const float*)d_in[1];   // [5120,160]
    const float* W2   = (const float*)d_in[2];   // [160,5120]
    const float* bias = (const float*)d_in[3];   // [5120]
    const float* Bp   = (const float*)d_in[4];   // [5120,16]
    const float* abar = (const float*)d_in[5];   // [256,5120,16]
    const float* hst  = (const float*)d_in[6];   // [256,5120,16]
    float* out = (float*)d_out;

    stage1_kernel<<<dim3(U_DIM / S1_UT, S1_SPLITS), 256>>>(x, W1, Bp);
    reduce_kernel<<<RED_F4 / 256, 256>>>();
    fused_kernel<<<dim3(U_DIM / FU_UT, D_DIM / FU_DT), 256>>>(
        W2, bias, x, (const float4*)abar, (const float4*)hst, (float4*)out);
}

// round 7
// speedup vs baseline: 1.0982x; 1.0370x over previous
#include <cuda_runtime.h>
#include <math.h>
#include <stdint.h>

// Shapes (fixed): U=256, D=5120, N=16, R=160
#define U_DIM 256
#define D_DIM 5120
#define N_DIM 16
#define R_DIM 160
#define NCOL  176   // 160 (t) + 16 (B)
#define NPAD  192   // padded col space: 3 col-pairs x 32 lanes

typedef unsigned long long ull;

// ---------------- scratch ----------------
#define S1_SPLITS 32
#define S1_KC     160     // K per split = 5 stages of 32
#define S1_KK     32      // K per smem stage
#define S1_NST    (S1_KC / S1_KK)   // 5
#define S1_UT     64      // users per block
#define XPITCH    66      // xsh pitch in ull (even -> 16B-aligned v2 reads)

__device__ float g_partial[S1_SPLITS * U_DIM * NCOL];   // 5.8 MB
__device__ float g_tbuf[U_DIM * NCOL];                  // t | B

// ---------------- helpers ----------------
__device__ __forceinline__ ull pack2(float v) {
    ull r; asm("mov.b64 %0, {%1, %1};" : "=l"(r) : "f"(v)); return r;
}
__device__ __forceinline__ ull combine2(float lo, float hi) {
    ull r; asm("mov.b64 %0, {%1, %2};" : "=l"(r) : "f"(lo), "f"(hi)); return r;
}
__device__ __forceinline__ void fma2(ull& acc, ull a, ull b) {
    asm("fma.rn.f32x2 %0, %1, %2, %0;" : "+l"(acc) : "l"(a), "l"(b));
}
__device__ __forceinline__ void lds_v2b64(ull& a, ull& b, uint32_t addr) {
    asm volatile("ld.shared.v2.b64 {%0, %1}, [%2];" : "=l"(a), "=l"(b) : "r"(addr));
}
__device__ __forceinline__ ull lds_b64(uint32_t addr) {
    ull a; asm volatile("ld.shared.b64 %0, [%1];" : "=l"(a) : "r"(addr)); return a;
}
__device__ __forceinline__ void cp16(uint32_t dst, const void* src) {
    asm volatile("cp.async.ca.shared.global [%0], [%1], 16;" :: "r"(dst), "l"(src));
}
__device__ __forceinline__ void cp_commit() {
    asm volatile("cp.async.commit_group;");
}
__device__ __forceinline__ void cp_wait0() {
    asm volatile("cp.async.wait_group 0;");
}
__device__ __forceinline__ void cp_wait1() {
    asm volatile("cp.async.wait_group 1;");
}

// ================= Stage 1: split-K GEMM  t_ext[U,176] = x @ [W1 | Bp] ==========
// grid (4 u-tiles, 32 k-splits) = 128 blocks (single wave), block 256 (8 warps).
// 5-stage pipeline: W via cp.async double buffer, x via register double buffer.
// Warp w owns users w*8..w*8+7. Lane cx owns col-pairs (64c + 2cx, +1), c=0..2.
__global__ void __launch_bounds__(256) stage1_kernel(
    const float* __restrict__ x,
    const float* __restrict__ W1,   // [5120,160]
    const float* __restrict__ Bp)   // [5120,16]
{
    __shared__ __align__(16) ull   xsh[2][S1_KK * XPITCH];    // {x,x} dup, 2x16.9KB
    __shared__ __align__(16) float wsh[2][S1_KK * NPAD];      // [k][col], 2x24.6KB

    const int tid = threadIdx.x;
    const int cx  = tid & 31;
    const int wid = tid >> 5;
    const int u0  = blockIdx.x * S1_UT;
    const int k0  = blockIdx.y * S1_KC;

    const uint32_t xb = (uint32_t)__cvta_generic_to_shared(xsh);
    const uint32_t wb = (uint32_t)__cvta_generic_to_shared(wsh);

    // per-thread x element coordinates (8 elements, coalesced)
    const int xu = tid >> 5;         // warp id -> base user row step
    const int xk = tid & 31;         // lane -> k within stage

    // W staging for stage s into buffer b
    auto stage_w = [&](int s, int b) {
        const int kb = k0 + s * S1_KK;
        const uint32_t wdst = wb + (uint32_t)(b * S1_KK * NPAD) * 4u;
        for (int ch = tid; ch < S1_KK * 40; ch += 256) {
            int k = ch / 40, c = ch - k * 40;
            cp16(wdst + (uint32_t)(k * NPAD + c * 4) * 4u,
                 W1 + (size_t)(kb + k) * R_DIM + c * 4);
        }
        if (tid < S1_KK * 4) {
            int k = tid >> 2, c = tid & 3;
            cp16(wdst + (uint32_t)(k * NPAD + R_DIM + c * 4) * 4u,
                 Bp + (size_t)(kb + k) * N_DIM + c * 4);
        }
        cp_commit();
    };
    // x LDG for stage s -> regs
    float xr[8];
    auto load_x = [&](int s) {
#pragma unroll
        for (int j = 0; j < 8; ++j) {
            int u = xu + j * 8;
            xr[j] = x[(size_t)(u0 + u) * D_DIM + k0 + s * S1_KK + xk];
        }
    };
    // STS x regs (duplicated) into buffer b
    auto sts_x = [&](int b) {
#pragma unroll
        for (int j = 0; j < 8; ++j)
            xsh[b][xk * XPITCH + xu + j * 8] = pack2(xr[j]);
    };

    ull acc[8][3];
#pragma unroll
    for (int uu = 0; uu < 8; ++uu)
#pragma unroll
        for (int c = 0; c < 3; ++c) acc[uu][c] = 0ULL;

    // prologue
    stage_w(0, 0);
    load_x(0);

#pragma unroll 1
    for (int s = 0; s < S1_NST; ++s) {
        const int b = s & 1;
        sts_x(b);
        if (s + 1 < S1_NST) stage_w(s + 1, 1 - b);
        if (s + 1 < S1_NST) cp_wait1(); else cp_wait0();
        __syncthreads();
        if (s + 1 < S1_NST) load_x(s + 1);

        const uint32_t xbase = xb + (uint32_t)(b * S1_KK * XPITCH) * 8u;
        const uint32_t wbase = wb + (uint32_t)(b * S1_KK * NPAD) * 4u;
#pragma unroll 4
        for (int kk = 0; kk < S1_KK; ++kk) {
            ull xp[8];
            const uint32_t xa = xbase + (uint32_t)(kk * XPITCH + wid * 8) * 8u;
            lds_v2b64(xp[0], xp[1], xa);
            lds_v2b64(xp[2], xp[3], xa + 16u);
            lds_v2b64(xp[4], xp[5], xa + 32u);
            lds_v2b64(xp[6], xp[7], xa + 48u);
            const uint32_t wa = wbase + (uint32_t)(kk * NPAD + 2 * cx) * 4u;
            ull wp[3];
            wp[0] = lds_b64(wa);
            wp[1] = lds_b64(wa + 256u);
            wp[2] = lds_b64(wa + 512u);
#pragma unroll
            for (int c = 0; c < 3; ++c)
#pragma unroll
                for (int uu = 0; uu < 8; ++uu) fma2(acc[uu][c], xp[uu], wp[c]);
        }
        __syncthreads();
    }

    // writeout: packed 8B stores of col-pairs (64c+2cx, +1); pair valid iff c<2 || cx<24
    float* pout = g_partial + (size_t)blockIdx.y * (U_DIM * NCOL);
#pragma unroll
    for (int uu = 0; uu < 8; ++uu) {
        const int u = u0 + wid * 8 + uu;
#pragma unroll
        for (int c = 0; c < 3; ++c) {
            if (c < 2 || cx < 24) {
                const int col = 64 * c + 2 * cx;
                *(ull*)(pout + (size_t)u * NCOL + col) = acc[uu][c];
            }
        }
    }
}

// ================= Stage 2: reduce 32 split partials (float4) ===================
#define RED_F4 (U_DIM * NCOL / 4)   // 11264
__global__ void __launch_bounds__(256) reduce_kernel() {
    const int idx = blockIdx.x * 256 + threadIdx.x;   // 44 * 256 == 11264 exactly
    const float4* p4 = (const float4*)g_partial;
    float4 s = make_float4(0.f, 0.f, 0.f, 0.f);
#pragma unroll
    for (int sp = 0; sp < S1_SPLITS; ++sp) {
        float4 v = __ldcg(p4 + (size_t)sp * RED_F4 + idx);
        s.x += v.x; s.y += v.y; s.z += v.z; s.w += v.w;
    }
    ((float4*)g_tbuf)[idx] = s;
}

// ================= Stage 3: fused dt-GEMM + softplus + streaming ================
// Block: 16 users x 128 d. W2 double-buffered via cp.async in 32-row chunks.
#define FU_UT 16
#define FU_DT 128
#define RCH 32                 // r rows per chunk
#define NCH (R_DIM / RCH)      // 5 chunks
#define W2CHUNK (RCH * FU_DT)  // floats per chunk (4096)

__global__ void __launch_bounds__(256, 4) fused_kernel(
    const float* __restrict__ W2,    // [160,5120]
    const float* __restrict__ bias,  // [5120]
    const float* __restrict__ x,     // [256,5120]
    const float4* __restrict__ abar4,
    const float4* __restrict__ hst4,
    float4* __restrict__ out4)
{
    __shared__ __align__(16) ull   tpair[R_DIM * 8];          // {t_u,t_u+1} 10.2 KB
    __shared__ __align__(16) float w2sh[2 * W2CHUNK];         // 32 KB ping-pong
    __shared__ __align__(16) float c1sh[FU_UT * FU_DT];       // 8 KB
    __shared__ __align__(16) float Bsh[FU_UT * N_DIM];        // 1 KB

    const int u0  = blockIdx.x * FU_UT;
    const int d0  = blockIdx.y * FU_DT;
    const int tid = threadIdx.x;

    const uint32_t w2b = (uint32_t)__cvta_generic_to_shared(w2sh);
    const uint32_t tpb = (uint32_t)__cvta_generic_to_shared(tpair);

    // prefetch W2 chunk 0 (rows 0..31): 1024 x 16B chunks, 4 per thread
    {
#pragma unroll
        for (int q = 0; q < 4; ++q) {
            int ch = tid + q * 256;
            int row = ch >> 5, c = ch & 31;
            cp16(w2b + (uint32_t)(row * FU_DT + c * 4) * 4u,
                 W2 + (size_t)row * D_DIM + d0 + c * 4);
        }
    }
    cp_commit();

    // stage t as user-pairs: tpair[r*8 + p] = {t[u0+2p][r], t[u0+2p+1][r]}
    for (int e = tid; e < R_DIM * 8; e += 256) {
        int r = e >> 3, p = e & 7;
        float lo = g_tbuf[(size_t)(u0 + 2 * p)     * NCOL + r];
        float hi = g_tbuf[(size_t)(u0 + 2 * p + 1) * NCOL + r];
        tpair[r * 8 + p] = combine2(lo, hi);
    }
    // stage B: tid covers 16u x 16n exactly
    {
        int u = tid >> 4, n = tid & 15;
        Bsh[tid] = g_tbuf[(size_t)(u0 + u) * NCOL + R_DIM + n];
    }

    // ---- GEMM phase: 5 chunks of 32 r, cp.async one-stage lookahead ----
    const int dl  = tid & 127;
    const int pg  = (tid >> 7) * 4;    // pair-group base: 0 or 4
    const int d   = d0 + dl;

    ull acc[4];
#pragma unroll
    for (int i = 0; i < 4; ++i) acc[i] = 0ULL;

#pragma unroll 1
    for (int s = 0; s < NCH; ++s) {
        cp_wait0();            // chunk s landed
        __syncthreads();       // everyone done with the buffer being overwritten
        if (s + 1 < NCH) {
#pragma unroll
            for (int q = 0; q < 4; ++q) {
                int ch = tid + q * 256;
                int row = ch >> 5, c = ch & 31;
                cp16(w2b + (uint32_t)(((s + 1) & 1) * W2CHUNK + row * FU_DT + c * 4) * 4u,
                     W2 + (size_t)((s + 1) * RCH + row) * D_DIM + d0 + c * 4);
            }
            cp_commit();
        }
        const uint32_t wbase = w2b + (uint32_t)((s & 1) * W2CHUNK + dl) * 4u;
        const uint32_t tbase = tpb + (uint32_t)(s * RCH * 8 + pg) * 8u;
#pragma unroll
        for (int rr = 0; rr < RCH; ++rr) {
            float wv;
            asm volatile("ld.shared.b32 %0, [%1];"
                         : "=f"(wv) : "r"(wbase + (uint32_t)(rr * FU_DT) * 4u));
            const ull w2 = pack2(wv);
            ull p0, p1, p2, p3;
            const uint32_t ta = tbase + (uint32_t)(rr * 8) * 8u;
            lds_v2b64(p0, p1, ta);
            lds_v2b64(p2, p3, ta + 16u);
            fma2(acc[0], p0, w2); fma2(acc[1], p1, w2);
            fma2(acc[2], p2, w2); fma2(acc[3], p3, w2);
        }
    }

    const float bz = bias[d];
    const int ug = (tid >> 7) * 8;
#pragma unroll
    for (int i = 0; i < 4; ++i) {
        float z0, z1;
        asm("mov.b64 {%0, %1}, %2;" : "=f"(z0), "=f"(z1) : "l"(acc[i]));
        const int u = ug + 2 * i;
        z0 += bz; z1 += bz;
        const float dt0 = fmaxf(z0, 0.f) + log1pf(expf(-fabsf(z0)));
        const float dt1 = fmaxf(z1, 0.f) + log1pf(expf(-fabsf(z1)));
        c1sh[u * FU_DT + dl]       = dt0 * __ldg(x + (size_t)(u0 + u) * D_DIM + d);
        c1sh[(u + 1) * FU_DT + dl] = dt1 * __ldg(x + (size_t)(u0 + u + 1) * D_DIM + d);
    }
    __syncthreads();

    // ---- streaming phase ----
    const int n4 = tid & 3;
    const int i0 = tid;
    const int i1 = tid + 256;

#pragma unroll 2
    for (int u = 0; u < FU_UT; ++u) {
        const size_t base = ((size_t)(u0 + u) * D_DIM + d0) * 4;  // float4 units
        const float4 b = *(const float4*)(Bsh + u * N_DIM + n4 * 4);
        const float c0 = c1sh[u * FU_DT + (i0 >> 2)];
        const float c1 = c1sh[u * FU_DT + (i1 >> 2)];

        const float4 a0 = __ldcs(abar4 + base + i0);
        const float4 h0 = __ldcs(hst4  + base + i0);
        const float4 a1 = __ldcs(abar4 + base + i1);
        const float4 h1 = __ldcs(hst4  + base + i1);

        float4 o0, o1;
        o0.x = fmaf(a0.x, h0.x, c0 * b.x);
        o0.y = fmaf(a0.y, h0.y, c0 * b.y);
        o0.z = fmaf(a0.z, h0.z, c0 * b.z);
        o0.w = fmaf(a0.w, h0.w, c0 * b.w);
        o1.x = fmaf(a1.x, h1.x, c1 * b.x);
        o1.y = fmaf(a1.y, h1.y, c1 * b.y);
        o1.z = fmaf(a1.z, h1.z, c1 * b.z);
        o1.w = fmaf(a1.w, h1.w, c1 * b.w);
        __stcs(out4 + base + i0, o0);
        __stcs(out4 + base + i1, o1);
    }
}

extern "C" void kernel_launch(void* const* d_in, const int* in_sizes, int n_in,
                              void* d_out, int out_size) {
    const float* x    = (const float*)d_in[0];   // [256,5120]
    const float* W1   = (const float*)d_in[1];   // [5120,160]
    const float* W2   = (const float*)d_in[2];   // [160,5120]
    const float* bias = (const float*)d_in[3];   // [5120]
    const float* Bp   = (const float*)d_in[4];   // [5120,16]
    const float* abar = (const float*)d_in[5];   // [256,5120,16]
    const float* hst  = (const float*)d_in[6];   // [256,5120,16]
    float* out = (float*)d_out;

    stage1_kernel<<<dim3(U_DIM / S1_UT, S1_SPLITS), 256>>>(x, W1, Bp);
    reduce_kernel<<<RED_F4 / 256, 256>>>();
    fused_kernel<<<dim3(U_DIM / FU_UT, D_DIM / FU_DT), 256>>>(
        W2, bias, x, (const float4*)abar, (const float4*)hst, (float4*)out);
}

// round 8
// speedup vs baseline: 1.3473x; 1.2268x over previous
#include <cuda_runtime.h>
#include <math.h>
#include <stdint.h>

// Shapes (fixed): U=256, D=5120, N=16, R=160
#define U_DIM 256
#define D_DIM 5120
#define N_DIM 16
#define R_DIM 160
#define NCOL  176   // 160 (t) + 16 (B)
#define NPAD  192   // padded col space: 3 col-pairs x 32 lanes

typedef unsigned long long ull;

// ---------------- scratch ----------------
#define S1_SPLITS 32
#define S1_KC     160     // K per split = 5 stages of 32
#define S1_KK     32      // K per smem stage
#define S1_NST    (S1_KC / S1_KK)   // 5
#define S1_UT     64      // users per block
#define S1_THREADS 512
#define XPITCH    66      // xsh pitch in ull (even -> 16B-aligned v2 reads)

__device__ float g_partial[S1_SPLITS * U_DIM * NCOL];   // 5.8 MB
__device__ float g_tbuf[U_DIM * NCOL];                  // t | B

// ---------------- helpers ----------------
__device__ __forceinline__ ull pack2(float v) {
    ull r; asm("mov.b64 %0, {%1, %1};" : "=l"(r) : "f"(v)); return r;
}
__device__ __forceinline__ ull combine2(float lo, float hi) {
    ull r; asm("mov.b64 %0, {%1, %2};" : "=l"(r) : "f"(lo), "f"(hi)); return r;
}
__device__ __forceinline__ void fma2(ull& acc, ull a, ull b) {
    asm("fma.rn.f32x2 %0, %1, %2, %0;" : "+l"(acc) : "l"(a), "l"(b));
}
__device__ __forceinline__ void lds_v2b64(ull& a, ull& b, uint32_t addr) {
    asm volatile("ld.shared.v2.b64 {%0, %1}, [%2];" : "=l"(a), "=l"(b) : "r"(addr));
}
__device__ __forceinline__ ull lds_b64(uint32_t addr) {
    ull a; asm volatile("ld.shared.b64 %0, [%1];" : "=l"(a) : "r"(addr)); return a;
}
__device__ __forceinline__ void cp16(uint32_t dst, const void* src) {
    asm volatile("cp.async.ca.shared.global [%0], [%1], 16;" :: "r"(dst), "l"(src));
}
__device__ __forceinline__ void cp_commit() {
    asm volatile("cp.async.commit_group;");
}
__device__ __forceinline__ void cp_wait0() {
    asm volatile("cp.async.wait_group 0;");
}
__device__ __forceinline__ void cp_wait1() {
    asm volatile("cp.async.wait_group 1;");
}

// ================= Stage 1: split-K GEMM  t_ext[U,176] = x @ [W1 | Bp] ==========
// grid (4 u-tiles, 32 k-splits) = 128 blocks (single wave), block 512 (16 warps).
// 5-stage pipeline: W via cp.async double buffer, x via register double buffer.
// Warp w owns users w*4..w*4+3. Lane cx owns col-pairs (64c + 2cx, +1), c=0..2.
__global__ void __launch_bounds__(S1_THREADS) stage1_kernel(
    const float* __restrict__ x,
    const float* __restrict__ W1,   // [5120,160]
    const float* __restrict__ Bp)   // [5120,16]
{
    __shared__ __align__(16) ull   xsh[2][S1_KK * XPITCH];    // {x,x} dup, 2x16.9KB
    __shared__ __align__(16) float wsh[2][S1_KK * NPAD];      // [k][col], 2x24.6KB

    const int tid = threadIdx.x;
    const int cx  = tid & 31;
    const int wid = tid >> 5;        // 0..15
    const int u0  = blockIdx.x * S1_UT;
    const int k0  = blockIdx.y * S1_KC;

    const uint32_t xb = (uint32_t)__cvta_generic_to_shared(xsh);
    const uint32_t wb = (uint32_t)__cvta_generic_to_shared(wsh);

    // per-thread x element coordinates (4 elements, coalesced)
    const int xu = tid >> 5;         // 0..15 base user
    const int xk = tid & 31;         // lane -> k within stage

    auto stage_w = [&](int s, int b) {
        const int kb = k0 + s * S1_KK;
        const uint32_t wdst = wb + (uint32_t)(b * S1_KK * NPAD) * 4u;
        for (int ch = tid; ch < S1_KK * 40; ch += S1_THREADS) {
            int k = ch / 40, c = ch - k * 40;
            cp16(wdst + (uint32_t)(k * NPAD + c * 4) * 4u,
                 W1 + (size_t)(kb + k) * R_DIM + c * 4);
        }
        if (tid < S1_KK * 4) {
            int k = tid >> 2, c = tid & 3;
            cp16(wdst + (uint32_t)(k * NPAD + R_DIM + c * 4) * 4u,
                 Bp + (size_t)(kb + k) * N_DIM + c * 4);
        }
        cp_commit();
    };
    float xr[4];
    auto load_x = [&](int s) {
#pragma unroll
        for (int j = 0; j < 4; ++j) {
            int u = xu + j * 16;
            xr[j] = x[(size_t)(u0 + u) * D_DIM + k0 + s * S1_KK + xk];
        }
    };
    auto sts_x = [&](int b) {
#pragma unroll
        for (int j = 0; j < 4; ++j)
            xsh[b][xk * XPITCH + xu + j * 16] = pack2(xr[j]);
    };

    ull acc[4][3];
#pragma unroll
    for (int uu = 0; uu < 4; ++uu)
#pragma unroll
        for (int c = 0; c < 3; ++c) acc[uu][c] = 0ULL;

    stage_w(0, 0);
    load_x(0);

#pragma unroll 1
    for (int s = 0; s < S1_NST; ++s) {
        const int b = s & 1;
        sts_x(b);
        if (s + 1 < S1_NST) stage_w(s + 1, 1 - b);
        if (s + 1 < S1_NST) cp_wait1(); else cp_wait0();
        __syncthreads();
        if (s + 1 < S1_NST) load_x(s + 1);

        const uint32_t xbase = xb + (uint32_t)(b * S1_KK * XPITCH) * 8u;
        const uint32_t wbase = wb + (uint32_t)(b * S1_KK * NPAD) * 4u;
#pragma unroll 4
        for (int kk = 0; kk < S1_KK; ++kk) {
            ull xp[4];
            const uint32_t xa = xbase + (uint32_t)(kk * XPITCH + wid * 4) * 8u;
            lds_v2b64(xp[0], xp[1], xa);
            lds_v2b64(xp[2], xp[3], xa + 16u);
            const uint32_t wa = wbase + (uint32_t)(kk * NPAD + 2 * cx) * 4u;
            ull wp[3];
            wp[0] = lds_b64(wa);
            wp[1] = lds_b64(wa + 256u);
            wp[2] = lds_b64(wa + 512u);
#pragma unroll
            for (int c = 0; c < 3; ++c)
#pragma unroll
                for (int uu = 0; uu < 4; ++uu) fma2(acc[uu][c], xp[uu], wp[c]);
        }
        __syncthreads();
    }

    // writeout: packed 8B stores of col-pairs (64c+2cx, +1); pair valid iff c<2 || cx<24
    float* pout = g_partial + (size_t)blockIdx.y * (U_DIM * NCOL);
#pragma unroll
    for (int uu = 0; uu < 4; ++uu) {
        const int u = u0 + wid * 4 + uu;
#pragma unroll
        for (int c = 0; c < 3; ++c) {
            if (c < 2 || cx < 24) {
                const int col = 64 * c + 2 * cx;
                *(ull*)(pout + (size_t)u * NCOL + col) = acc[uu][c];
            }
        }
    }
}

// ================= Stage 2: reduce 32 split partials (float4) ===================
#define RED_F4 (U_DIM * NCOL / 4)   // 11264
__global__ void __launch_bounds__(256) reduce_kernel() {
    const int idx = blockIdx.x * 256 + threadIdx.x;   // 44 * 256 == 11264 exactly
    const float4* p4 = (const float4*)g_partial;
    float4 s = make_float4(0.f, 0.f, 0.f, 0.f);
#pragma unroll
    for (int sp = 0; sp < S1_SPLITS; ++sp) {
        float4 v = __ldcg(p4 + (size_t)sp * RED_F4 + idx);
        s.x += v.x; s.y += v.y; s.z += v.z; s.w += v.w;
    }
    ((float4*)g_tbuf)[idx] = s;
}

// ================= Stage 3: fused dt-GEMM + softplus + streaming ================
// Block: 8 users x 128 d. W2 double-buffered via cp.async in 16-row chunks.
// grid 1280 (1.44 waves at 6 blocks/SM) -> wave-2 GEMM overlaps wave-1 streaming.
#define FU_UT 8
#define FU_DT 128
#define RCH 16                 // r rows per chunk
#define NCH (R_DIM / RCH)      // 10 chunks
#define W2CHUNK (RCH * FU_DT)  // floats per chunk (2048)

__global__ void __launch_bounds__(256, 6) fused_kernel(
    const float* __restrict__ W2,    // [160,5120]
    const float* __restrict__ bias,  // [5120]
    const float* __restrict__ x,     // [256,5120]
    const float4* __restrict__ abar4,
    const float4* __restrict__ hst4,
    float4* __restrict__ out4)
{
    __shared__ __align__(16) ull   tpair[R_DIM * 4];          // {t_u,t_u+1} 5.1 KB
    __shared__ __align__(16) float w2sh[2 * W2CHUNK];         // 16 KB ping-pong
    __shared__ __align__(16) float c1sh[FU_UT * FU_DT];       // 4 KB
    __shared__ __align__(16) float Bsh[FU_UT * N_DIM];        // 0.5 KB

    const int u0  = blockIdx.x * FU_UT;
    const int d0  = blockIdx.y * FU_DT;
    const int tid = threadIdx.x;

    const uint32_t w2b = (uint32_t)__cvta_generic_to_shared(w2sh);
    const uint32_t tpb = (uint32_t)__cvta_generic_to_shared(tpair);

    // prefetch W2 chunk 0 (rows 0..15): 512 x 16B chunks, 2 per thread
    {
#pragma unroll
        for (int q = 0; q < 2; ++q) {
            int ch = tid + q * 256;
            int row = ch >> 5, c = ch & 31;
            cp16(w2b + (uint32_t)(row * FU_DT + c * 4) * 4u,
                 W2 + (size_t)row * D_DIM + d0 + c * 4);
        }
    }
    cp_commit();

    // stage t as user-pairs: tpair[r*4 + p] = {t[u0+2p][r], t[u0+2p+1][r]}
    for (int e = tid; e < R_DIM * 4; e += 256) {
        int r = e >> 2, p = e & 3;
        float lo = g_tbuf[(size_t)(u0 + 2 * p)     * NCOL + r];
        float hi = g_tbuf[(size_t)(u0 + 2 * p + 1) * NCOL + r];
        tpair[r * 4 + p] = combine2(lo, hi);
    }
    // stage B: 8u x 16n = 128 entries
    if (tid < FU_UT * N_DIM) {
        int u = tid >> 4, n = tid & 15;
        Bsh[tid] = g_tbuf[(size_t)(u0 + u) * NCOL + R_DIM + n];
    }

    // ---- GEMM phase: 10 chunks of 16 r, cp.async one-stage lookahead ----
    const int dl = tid & 127;
    const int g  = tid >> 7;       // 0 or 1
    const int pg = g * 2;          // pair-group base
    const int d  = d0 + dl;

    ull acc[2];
    acc[0] = 0ULL; acc[1] = 0ULL;

#pragma unroll 1
    for (int s = 0; s < NCH; ++s) {
        cp_wait0();            // chunk s landed
        __syncthreads();       // everyone done with the buffer being overwritten
        if (s + 1 < NCH) {
#pragma unroll
            for (int q = 0; q < 2; ++q) {
                int ch = tid + q * 256;
                int row = ch >> 5, c = ch & 31;
                cp16(w2b + (uint32_t)(((s + 1) & 1) * W2CHUNK + row * FU_DT + c * 4) * 4u,
                     W2 + (size_t)((s + 1) * RCH + row) * D_DIM + d0 + c * 4);
            }
            cp_commit();
        }
        const uint32_t wbase = w2b + (uint32_t)((s & 1) * W2CHUNK + dl) * 4u;
        const uint32_t tbase = tpb + (uint32_t)(s * RCH * 4 + pg) * 8u;
#pragma unroll
        for (int rr = 0; rr < RCH; ++rr) {
            float wv;
            asm volatile("ld.shared.b32 %0, [%1];"
                         : "=f"(wv) : "r"(wbase + (uint32_t)(rr * FU_DT) * 4u));
            const ull w2 = pack2(wv);
            ull p0, p1;
            lds_v2b64(p0, p1, tbase + (uint32_t)(rr * 4) * 8u);
            fma2(acc[0], p0, w2);
            fma2(acc[1], p1, w2);
        }
    }

    const float bz = bias[d];
    const int ug = g * 4;
#pragma unroll
    for (int i = 0; i < 2; ++i) {
        float z0, z1;
        asm("mov.b64 {%0, %1}, %2;" : "=f"(z0), "=f"(z1) : "l"(acc[i]));
        const int u = ug + 2 * i;
        z0 += bz; z1 += bz;
        const float dt0 = fmaxf(z0, 0.f) + log1pf(expf(-fabsf(z0)));
        const float dt1 = fmaxf(z1, 0.f) + log1pf(expf(-fabsf(z1)));
        c1sh[u * FU_DT + dl]       = dt0 * __ldg(x + (size_t)(u0 + u) * D_DIM + d);
        c1sh[(u + 1) * FU_DT + dl] = dt1 * __ldg(x + (size_t)(u0 + u + 1) * D_DIM + d);
    }
    __syncthreads();

    // ---- streaming phase ----
    const int n4 = tid & 3;
    const int i0 = tid;
    const int i1 = tid + 256;

#pragma unroll 2
    for (int u = 0; u < FU_UT; ++u) {
        const size_t base = ((size_t)(u0 + u) * D_DIM + d0) * 4;  // float4 units
        const float4 b = *(const float4*)(Bsh + u * N_DIM + n4 * 4);
        const float c0 = c1sh[u * FU_DT + (i0 >> 2)];
        const float c1 = c1sh[u * FU_DT + (i1 >> 2)];

        const float4 a0 = __ldcs(abar4 + base + i0);
        const float4 h0 = __ldcs(hst4  + base + i0);
        const float4 a1 = __ldcs(abar4 + base + i1);
        const float4 h1 = __ldcs(hst4  + base + i1);

        float4 o0, o1;
        o0.x = fmaf(a0.x, h0.x, c0 * b.x);
        o0.y = fmaf(a0.y, h0.y, c0 * b.y);
        o0.z = fmaf(a0.z, h0.z, c0 * b.z);
        o0.w = fmaf(a0.w, h0.w, c0 * b.w);
        o1.x = fmaf(a1.x, h1.x, c1 * b.x);
        o1.y = fmaf(a1.y, h1.y, c1 * b.y);
        o1.z = fmaf(a1.z, h1.z, c1 * b.z);
        o1.w = fmaf(a1.w, h1.w, c1 * b.w);
        __stcs(out4 + base + i0, o0);
        __stcs(out4 + base + i1, o1);
    }
}

extern "C" void kernel_launch(void* const* d_in, const int* in_sizes, int n_in,
                              void* d_out, int out_size) {
    const float* x    = (const float*)d_in[0];   // [256,5120]
    const float* W1   = (const float*)d_in[1];   // [5120,160]
    const float* W2   = (const float*)d_in[2];   // [160,5120]
    const float* bias = (const float*)d_in[3];   // [5120]
    const float* Bp   = (const float*)d_in[4];   // [5120,16]
    const float* abar = (const float*)d_in[5];   // [256,5120,16]
    const float* hst  = (const float*)d_in[6];   // [256,5120,16]
    float* out = (float*)d_out;

    stage1_kernel<<<dim3(U_DIM / S1_UT, S1_SPLITS), S1_THREADS>>>(x, W1, Bp);
    reduce_kernel<<<RED_F4 / 256, 256>>>();
    fused_kernel<<<dim3(U_DIM / FU_UT, D_DIM / FU_DT), 256>>>(
        W2, bias, x, (const float4*)abar, (const float4*)hst, (float4*)out);
}